// round 9
// baseline (speedup 1.0000x reference)
#include <cuda_runtime.h>
#include <cuda_bf16.h>
#include <cstdint>

#define N_NODES   50000
#define N_PAD     50048          // 391 * 128
#define DEG       16
#define IN_F      256
#define OUT_C     256            // NUM_HEADS * OUT_FEATS
#define NUM_HEADS 4
#define OUT_F     64
#define NEG_SLOPE 0.2f

// ---------------- scratch (static device globals; no allocation) ------------
__device__ float g_wt[(size_t)OUT_C * IN_F];            // W^T [n][k], tf32-rounded
__device__ float g_h [(size_t)N_PAD * OUT_C];           // projected features
__device__ float g_sl[(size_t)N_PAD * NUM_HEADS];       // dst scores
__device__ float g_sr[(size_t)N_PAD * NUM_HEADS];       // src scores

__device__ __forceinline__ uint32_t smem_u32(const void* p) {
    uint32_t a;
    asm("{ .reg .u64 t; cvta.to.shared.u64 t, %1; cvt.u32.u64 %0, t; }" : "=r"(a) : "l"(p));
    return a;
}

__device__ __forceinline__ void ldsm_x4(uint32_t* f, uint32_t addr) {
    asm volatile("ldmatrix.sync.aligned.m8n8.x4.shared.b16 {%0,%1,%2,%3}, [%4];"
                 : "=r"(f[0]), "=r"(f[1]), "=r"(f[2]), "=r"(f[3]) : "r"(addr));
}

__device__ __forceinline__ void mma_tf32(float* c, const uint32_t* a,
                                         uint32_t b0, uint32_t b1) {
    asm volatile("mma.sync.aligned.m16n8k8.row.col.f32.tf32.tf32.f32 "
                 "{%0,%1,%2,%3}, {%4,%5,%6,%7}, {%8,%9}, {%0,%1,%2,%3};"
                 : "+f"(c[0]), "+f"(c[1]), "+f"(c[2]), "+f"(c[3])
                 : "r"(a[0]), "r"(a[1]), "r"(a[2]), "r"(a[3]), "r"(b0), "r"(b1));
}

__device__ __forceinline__ float to_tf32(float x) {
    uint32_t u;
    asm("cvt.rna.tf32.f32 %0, %1;" : "=r"(u) : "f"(x));
    return __uint_as_float(u);
}

// ---------------------------------------------------------------------------
// Kernel B: transpose W [k][n] -> g_wt [n][k], tf32-rounded (256KB, ~4us)
// ---------------------------------------------------------------------------
__global__ __launch_bounds__(256) void gat_transpose_w(const float* __restrict__ W)
{
    __shared__ float tile[32][33];
    const int bk = blockIdx.x * 32;
    const int bn = blockIdx.y * 32;
    const int tx = threadIdx.x & 31;
    const int ty = threadIdx.x >> 5;
    #pragma unroll
    for (int j = 0; j < 32; j += 8)
        tile[ty + j][tx] = W[(size_t)(bk + ty + j) * OUT_C + bn + tx];
    __syncthreads();
    #pragma unroll
    for (int j = 0; j < 32; j += 8)
        g_wt[(size_t)(bn + ty + j) * IN_F + bk + tx] = to_tf32(tile[tx][ty + j]);
}

// ---------------------------------------------------------------------------
// Kernel C: 1xTF32 mma.sync GEMM h = feat @ W, fp32 accum.
// Round-6 structure, k-chunk widened to 64 (4 chunks, half the syncs).
// CTA = 128(M) x 128(N); 8 warps 2(m) x 4(n); warp tile 64x32; 2 CTAs/SM.
// Dynamic smem: A,B tiles 128 x 64 f32, row stride 68 (272B = 16B mod 128B
// -> 8 ldmatrix row pointers hit banks {0,4,...,28}, conflict-free).
// Epilogue: g_h + fused attn score dots.
// ---------------------------------------------------------------------------
#define ASTR  68
#define BUFE  (128 * ASTR)          // 8704 f32 per tile
#define DSMEM (2 * BUFE * 4)        // 69632 bytes

__global__ __launch_bounds__(256, 2) void gat_mma_kernel(
    const float* __restrict__ feat,
    const float* __restrict__ attn_l,
    const float* __restrict__ attn_r,
    int M)
{
    extern __shared__ __align__(16) float dsm[];
    float* const sA = dsm;
    float* const sB = dsm + BUFE;
    __shared__ float s_sl[128][2][2];
    __shared__ float s_sr[128][2][2];

    const int tid  = threadIdx.x;
    const int wid  = tid >> 5;
    const int lane = tid & 31;
    const int bm   = blockIdx.x * 128;
    const int bn   = blockIdx.y * 128;
    const int wm   = wid >> 2;
    const int wn   = wid & 3;

    const uint32_t sA_b = smem_u32(sA);
    const uint32_t sB_b = smem_u32(sB);

    float acc[4][4][4];
    #pragma unroll
    for (int mt = 0; mt < 4; mt++)
        #pragma unroll
        for (int nt = 0; nt < 4; nt++)
            #pragma unroll
            for (int r = 0; r < 4; r++) acc[mt][nt][r] = 0.f;

    // loader: each thread owns one half-row (32 f32) of the 128x64 tile
    const int lrow = tid >> 1;
    const int lcol = (tid & 1) * 32;
    const bool arow_ok = (bm + lrow) < M;
    const float* aptr = feat + (size_t)(bm + lrow) * IN_F + lcol;
    const float* bptr = g_wt + (size_t)(bn + lrow) * IN_F + lcol;
    float* const sA_st = sA + lrow * ASTR + lcol;
    float* const sB_st = sB + lrow * ASTR + lcol;

    const int mi  = lane >> 3;
    const int aro = ((mi & 1) << 3) + (lane & 7);
    const int aco = (mi >> 1) << 2;
    const int bro = ((mi >> 1) << 3) + (lane & 7);
    const int bco = (mi & 1) << 2;

    for (int c = 0; c < 4; c++) {                    // k-chunks of 64
        __syncthreads();
        #pragma unroll
        for (int j = 0; j < 8; j++) {
            float4 a = arow_ok ? *reinterpret_cast<const float4*>(aptr + c * 64 + j * 4)
                               : make_float4(0.f, 0.f, 0.f, 0.f);
            float4 b = *reinterpret_cast<const float4*>(bptr + c * 64 + j * 4);
            *reinterpret_cast<float4*>(sA_st + j * 4) =
                make_float4(to_tf32(a.x), to_tf32(a.y), to_tf32(a.z), to_tf32(a.w));
            *reinterpret_cast<float4*>(sB_st + j * 4) = b;   // pre-rounded
        }
        __syncthreads();

        #pragma unroll
        for (int ks = 0; ks < 8; ks++) {             // eight k8 steps
            uint32_t af[4][4];
            uint32_t bf[2][4];
            #pragma unroll
            for (int bp = 0; bp < 2; bp++) {
                int r = wn * 32 + bp * 16 + bro;
                uint32_t off = (uint32_t)(r * ASTR + ks * 8 + bco) * 4;
                ldsm_x4(bf[bp], sB_b + off);
            }
            #pragma unroll
            for (int mt = 0; mt < 4; mt++) {
                int r = wm * 64 + mt * 16 + aro;
                uint32_t off = (uint32_t)(r * ASTR + ks * 8 + aco) * 4;
                ldsm_x4(af[mt], sA_b + off);
            }
            #pragma unroll
            for (int mt = 0; mt < 4; mt++)
                #pragma unroll
                for (int nt = 0; nt < 4; nt++)
                    mma_tf32(acc[mt][nt], af[mt],
                             bf[nt >> 1][(nt & 1) * 2],
                             bf[nt >> 1][(nt & 1) * 2 + 1]);
        }
    }

    // ---- epilogue: store g_h + fused score dots (proven) --------------------
    const int hdl = wn >> 1;
    const int wp  = wn & 1;

    float alv[4][2], arv[4][2];
    #pragma unroll
    for (int nt = 0; nt < 4; nt++) {
        int col = bn + wn * 32 + nt * 8 + (lane & 3) * 2;
        alv[nt][0] = attn_l[col];     alv[nt][1] = attn_l[col + 1];
        arv[nt][0] = attn_r[col];     arv[nt][1] = attn_r[col + 1];
    }

    #pragma unroll
    for (int mt = 0; mt < 4; mt++) {
        int r0 = wm * 64 + mt * 16 + (lane >> 2);
        int r8 = r0 + 8;
        float sl0 = 0.f, sl8 = 0.f, sr0 = 0.f, sr8 = 0.f;
        #pragma unroll
        for (int nt = 0; nt < 4; nt++) {
            int col = bn + wn * 32 + nt * 8 + (lane & 3) * 2;
            float2 v0 = make_float2(acc[mt][nt][0], acc[mt][nt][1]);
            float2 v8 = make_float2(acc[mt][nt][2], acc[mt][nt][3]);
            *reinterpret_cast<float2*>(&g_h[(size_t)(bm + r0) * OUT_C + col]) = v0;
            *reinterpret_cast<float2*>(&g_h[(size_t)(bm + r8) * OUT_C + col]) = v8;
            sl0 += alv[nt][0] * v0.x + alv[nt][1] * v0.y;
            sl8 += alv[nt][0] * v8.x + alv[nt][1] * v8.y;
            sr0 += arv[nt][0] * v0.x + arv[nt][1] * v0.y;
            sr8 += arv[nt][0] * v8.x + arv[nt][1] * v8.y;
        }
        #pragma unroll
        for (int off = 1; off < 4; off <<= 1) {
            sl0 += __shfl_xor_sync(0xffffffffu, sl0, off);
            sl8 += __shfl_xor_sync(0xffffffffu, sl8, off);
            sr0 += __shfl_xor_sync(0xffffffffu, sr0, off);
            sr8 += __shfl_xor_sync(0xffffffffu, sr8, off);
        }
        if ((lane & 3) == 0) {
            s_sl[r0][hdl][wp] = sl0;  s_sl[r8][hdl][wp] = sl8;
            s_sr[r0][hdl][wp] = sr0;  s_sr[r8][hdl][wp] = sr8;
        }
    }
    __syncthreads();

    if (tid < 128) {
        int gr = bm + tid;
        int hb = bn >> 6;
        g_sl[(size_t)gr * 4 + hb + 0] = s_sl[tid][0][0] + s_sl[tid][0][1];
        g_sl[(size_t)gr * 4 + hb + 1] = s_sl[tid][1][0] + s_sl[tid][1][1];
        g_sr[(size_t)gr * 4 + hb + 0] = s_sr[tid][0][0] + s_sr[tid][0][1];
        g_sr[(size_t)gr * 4 + hb + 1] = s_sr[tid][1][0] + s_sr[tid][1][1];
    }
}

// ---------------------------------------------------------------------------
// Kernel D: softmax + aggregation (EXACT round-2 proven code, 54us).
// 64 threads per node, 4 nodes per block, default occupancy.
// ---------------------------------------------------------------------------
__global__ __launch_bounds__(256) void gat_agg_kernel(
    const int*    __restrict__ col_ind,
    const float4* __restrict__ h4,
    const float4* __restrict__ sl4,
    const float4* __restrict__ sr4,
    float4*       __restrict__ out4)
{
    const int local = threadIdx.x >> 6;
    const int t     = threadIdx.x & 63;
    const int n     = blockIdx.x * 4 + local;

    __shared__ int   ssrc  [4][16];
    __shared__ float salpha[4][16][4];

    if (t < 16) {
        int s = col_ind[n * DEG + t];
        ssrc[local][t] = s;
        float4 l = sl4[n];
        float4 r = sr4[s];
        float e0 = l.x + r.x, e1 = l.y + r.y, e2 = l.z + r.z, e3 = l.w + r.w;
        e0 = (e0 > 0.f) ? e0 : NEG_SLOPE * e0;
        e1 = (e1 > 0.f) ? e1 : NEG_SLOPE * e1;
        e2 = (e2 > 0.f) ? e2 : NEG_SLOPE * e2;
        e3 = (e3 > 0.f) ? e3 : NEG_SLOPE * e3;
        float m0 = e0, m1 = e1, m2 = e2, m3 = e3;
        #pragma unroll
        for (int off = 8; off > 0; off >>= 1) {
            m0 = fmaxf(m0, __shfl_xor_sync(0xffffu, m0, off));
            m1 = fmaxf(m1, __shfl_xor_sync(0xffffu, m1, off));
            m2 = fmaxf(m2, __shfl_xor_sync(0xffffu, m2, off));
            m3 = fmaxf(m3, __shfl_xor_sync(0xffffu, m3, off));
        }
        float x0 = __expf(e0 - m0), x1 = __expf(e1 - m1);
        float x2 = __expf(e2 - m2), x3 = __expf(e3 - m3);
        float s0 = x0, s1 = x1, s2 = x2, s3 = x3;
        #pragma unroll
        for (int off = 8; off > 0; off >>= 1) {
            s0 += __shfl_xor_sync(0xffffu, s0, off);
            s1 += __shfl_xor_sync(0xffffu, s1, off);
            s2 += __shfl_xor_sync(0xffffu, s2, off);
            s3 += __shfl_xor_sync(0xffffu, s3, off);
        }
        *reinterpret_cast<float4*>(&salpha[local][t][0]) =
            make_float4(x0 / s0, x1 / s1, x2 / s2, x3 / s3);
    }
    __syncthreads();

    const int hd = t >> 4;
    float4 acc = make_float4(0.f, 0.f, 0.f, 0.f);
    #pragma unroll
    for (int k = 0; k < DEG; k++) {
        float  a = salpha[local][k][hd];
        float4 v = h4[(size_t)ssrc[local][k] * 64 + t];
        acc.x += a * v.x;
        acc.y += a * v.y;
        acc.z += a * v.z;
        acc.w += a * v.w;
    }
    out4[(size_t)n * 64 + t] = acc;
}

// ---------------------------------------------------------------------------
// Launch. Inputs: row_ptr, col_ind, col_ptr, row_ind, feat, W, attn_l, attn_r
// ---------------------------------------------------------------------------
extern "C" void kernel_launch(void* const* d_in, const int* in_sizes, int n_in,
                              void* d_out, int out_size)
{
    const int*   col_ind = (const int*)  d_in[1];
    const float* feat    = (const float*)d_in[4];
    const float* W       = (const float*)d_in[5];
    const float* attn_l  = (const float*)d_in[6];
    const float* attn_r  = (const float*)d_in[7];
    float*       out     = (float*)      d_out;

    const int M = in_sizes[4] / IN_F;    // 50000

    float *h_ptr = nullptr, *sl_ptr = nullptr, *sr_ptr = nullptr;
    cudaGetSymbolAddress((void**)&h_ptr,  g_h);
    cudaGetSymbolAddress((void**)&sl_ptr, g_sl);
    cudaGetSymbolAddress((void**)&sr_ptr, g_sr);

    cudaFuncSetAttribute(gat_mma_kernel,
                         cudaFuncAttributeMaxDynamicSharedMemorySize, DSMEM);

    dim3 gtw(IN_F / 32, OUT_C / 32);
    gat_transpose_w<<<gtw, 256>>>(W);

    dim3 gmm(N_PAD / 128, 2);
    gat_mma_kernel<<<gmm, 256, DSMEM>>>(feat, attn_l, attn_r, M);

    gat_agg_kernel<<<M / 4, 256>>>(col_ind,
                                   (const float4*)h_ptr,
                                   (const float4*)sl_ptr,
                                   (const float4*)sr_ptr,
                                   (float4*)out);
}

// round 10
// speedup vs baseline: 1.2756x; 1.2756x over previous
#include <cuda_runtime.h>
#include <cuda_bf16.h>
#include <cstdint>

#define N_NODES   50000
#define N_PAD     50048          // 391 * 128
#define DEG       16
#define IN_F      256
#define OUT_C     256            // NUM_HEADS * OUT_FEATS
#define NUM_HEADS 4
#define OUT_F     64
#define NEG_SLOPE 0.2f

// ---------------- scratch (static device globals; no allocation) ------------
__device__ float g_wt[(size_t)OUT_C * IN_F];            // W^T [n][k], tf32-rounded
__device__ float g_h [(size_t)N_PAD * OUT_C];           // projected features
__device__ float g_sl[(size_t)N_PAD * NUM_HEADS];       // dst scores
__device__ float g_sr[(size_t)N_PAD * NUM_HEADS];       // src scores

__device__ __forceinline__ uint32_t smem_u32(const void* p) {
    uint32_t a;
    asm("{ .reg .u64 t; cvta.to.shared.u64 t, %1; cvt.u32.u64 %0, t; }" : "=r"(a) : "l"(p));
    return a;
}

__device__ __forceinline__ void ldsm_x4(uint32_t* f, uint32_t addr) {
    asm volatile("ldmatrix.sync.aligned.m8n8.x4.shared.b16 {%0,%1,%2,%3}, [%4];"
                 : "=r"(f[0]), "=r"(f[1]), "=r"(f[2]), "=r"(f[3]) : "r"(addr));
}

__device__ __forceinline__ void mma_tf32(float* c, const uint32_t* a,
                                         uint32_t b0, uint32_t b1) {
    asm volatile("mma.sync.aligned.m16n8k8.row.col.f32.tf32.tf32.f32 "
                 "{%0,%1,%2,%3}, {%4,%5,%6,%7}, {%8,%9}, {%0,%1,%2,%3};"
                 : "+f"(c[0]), "+f"(c[1]), "+f"(c[2]), "+f"(c[3])
                 : "r"(a[0]), "r"(a[1]), "r"(a[2]), "r"(a[3]), "r"(b0), "r"(b1));
}

__device__ __forceinline__ float to_tf32(float x) {
    uint32_t u;
    asm("cvt.rna.tf32.f32 %0, %1;" : "=r"(u) : "f"(x));
    return __uint_as_float(u);
}

// ---------------------------------------------------------------------------
// Kernel B: transpose W [k][n] -> g_wt [n][k], tf32-rounded (256KB, ~4us)
// ---------------------------------------------------------------------------
__global__ __launch_bounds__(256) void gat_transpose_w(const float* __restrict__ W)
{
    __shared__ float tile[32][33];
    const int bk = blockIdx.x * 32;
    const int bn = blockIdx.y * 32;
    const int tx = threadIdx.x & 31;
    const int ty = threadIdx.x >> 5;
    #pragma unroll
    for (int j = 0; j < 32; j += 8)
        tile[ty + j][tx] = W[(size_t)(bk + ty + j) * OUT_C + bn + tx];
    __syncthreads();
    #pragma unroll
    for (int j = 0; j < 32; j += 8)
        g_wt[(size_t)(bn + ty + j) * IN_F + bk + tx] = to_tf32(tile[tx][ty + j]);
}

// ---------------------------------------------------------------------------
// Kernel C (round-6 PROVEN, frozen): 1xTF32 mma.sync GEMM h = feat @ W.
// CTA = 128(M) x 128(N); 8 warps 2(m) x 4(n); warp tile 64x32; k-chunk 32.
// Static smem, stride 36 f32, single-buffered, 2 CTAs/SM.
// Epilogue: g_h + fused attn score dots.
// ---------------------------------------------------------------------------
#define ASTR 36

__global__ __launch_bounds__(256, 2) void gat_mma_kernel(
    const float* __restrict__ feat,
    const float* __restrict__ attn_l,
    const float* __restrict__ attn_r,
    int M)
{
    __shared__ __align__(16) float sA[128 * ASTR];
    __shared__ __align__(16) float sB[128 * ASTR];
    __shared__ float s_sl[128][2][2];
    __shared__ float s_sr[128][2][2];

    const int tid  = threadIdx.x;
    const int wid  = tid >> 5;
    const int lane = tid & 31;
    const int bm   = blockIdx.x * 128;
    const int bn   = blockIdx.y * 128;
    const int wm   = wid >> 2;
    const int wn   = wid & 3;

    const uint32_t sA_b = smem_u32(sA);
    const uint32_t sB_b = smem_u32(sB);

    float acc[4][4][4];
    #pragma unroll
    for (int mt = 0; mt < 4; mt++)
        #pragma unroll
        for (int nt = 0; nt < 4; nt++)
            #pragma unroll
            for (int r = 0; r < 4; r++) acc[mt][nt][r] = 0.f;

    const int lrow = tid >> 1;
    const int lcol = (tid & 1) * 16;
    const bool arow_ok = (bm + lrow) < M;
    const float* aptr = feat + (size_t)(bm + lrow) * IN_F + lcol;
    const float* bptr = g_wt + (size_t)(bn + lrow) * IN_F + lcol;
    float* const sA_st = sA + lrow * ASTR + lcol;
    float* const sB_st = sB + lrow * ASTR + lcol;

    const int mi  = lane >> 3;
    const int aro = ((mi & 1) << 3) + (lane & 7);
    const int aco = (mi >> 1) << 2;
    const int bro = ((mi >> 1) << 3) + (lane & 7);
    const int bco = (mi & 1) << 2;

    for (int c = 0; c < 8; c++) {
        __syncthreads();
        {
            float4 a0, a1, a2, a3;
            if (arow_ok) {
                a0 = *reinterpret_cast<const float4*>(aptr + c * 32);
                a1 = *reinterpret_cast<const float4*>(aptr + c * 32 + 4);
                a2 = *reinterpret_cast<const float4*>(aptr + c * 32 + 8);
                a3 = *reinterpret_cast<const float4*>(aptr + c * 32 + 12);
            } else {
                a0 = a1 = a2 = a3 = make_float4(0.f, 0.f, 0.f, 0.f);
            }
            float4 b0 = *reinterpret_cast<const float4*>(bptr + c * 32);
            float4 b1 = *reinterpret_cast<const float4*>(bptr + c * 32 + 4);
            float4 b2 = *reinterpret_cast<const float4*>(bptr + c * 32 + 8);
            float4 b3 = *reinterpret_cast<const float4*>(bptr + c * 32 + 12);
            *reinterpret_cast<float4*>(sA_st)      = make_float4(to_tf32(a0.x), to_tf32(a0.y), to_tf32(a0.z), to_tf32(a0.w));
            *reinterpret_cast<float4*>(sA_st + 4)  = make_float4(to_tf32(a1.x), to_tf32(a1.y), to_tf32(a1.z), to_tf32(a1.w));
            *reinterpret_cast<float4*>(sA_st + 8)  = make_float4(to_tf32(a2.x), to_tf32(a2.y), to_tf32(a2.z), to_tf32(a2.w));
            *reinterpret_cast<float4*>(sA_st + 12) = make_float4(to_tf32(a3.x), to_tf32(a3.y), to_tf32(a3.z), to_tf32(a3.w));
            *reinterpret_cast<float4*>(sB_st)      = b0;
            *reinterpret_cast<float4*>(sB_st + 4)  = b1;
            *reinterpret_cast<float4*>(sB_st + 8)  = b2;
            *reinterpret_cast<float4*>(sB_st + 12) = b3;
        }
        __syncthreads();

        #pragma unroll
        for (int ks = 0; ks < 4; ks++) {
            uint32_t af[4][4];
            uint32_t bf[2][4];
            #pragma unroll
            for (int bp = 0; bp < 2; bp++) {
                int r = wn * 32 + bp * 16 + bro;
                uint32_t off = (uint32_t)(r * ASTR + ks * 8 + bco) * 4;
                ldsm_x4(bf[bp], sB_b + off);
            }
            #pragma unroll
            for (int mt = 0; mt < 4; mt++) {
                int r = wm * 64 + mt * 16 + aro;
                uint32_t off = (uint32_t)(r * ASTR + ks * 8 + aco) * 4;
                ldsm_x4(af[mt], sA_b + off);
            }
            #pragma unroll
            for (int mt = 0; mt < 4; mt++)
                #pragma unroll
                for (int nt = 0; nt < 4; nt++)
                    mma_tf32(acc[mt][nt], af[mt],
                             bf[nt >> 1][(nt & 1) * 2],
                             bf[nt >> 1][(nt & 1) * 2 + 1]);
        }
    }

    // ---- epilogue: store g_h + fused score dots -----------------------------
    const int hdl = wn >> 1;
    const int wp  = wn & 1;

    float alv[4][2], arv[4][2];
    #pragma unroll
    for (int nt = 0; nt < 4; nt++) {
        int col = bn + wn * 32 + nt * 8 + (lane & 3) * 2;
        alv[nt][0] = attn_l[col];     alv[nt][1] = attn_l[col + 1];
        arv[nt][0] = attn_r[col];     arv[nt][1] = attn_r[col + 1];
    }

    #pragma unroll
    for (int mt = 0; mt < 4; mt++) {
        int r0 = wm * 64 + mt * 16 + (lane >> 2);
        int r8 = r0 + 8;
        float sl0 = 0.f, sl8 = 0.f, sr0 = 0.f, sr8 = 0.f;
        #pragma unroll
        for (int nt = 0; nt < 4; nt++) {
            int col = bn + wn * 32 + nt * 8 + (lane & 3) * 2;
            float2 v0 = make_float2(acc[mt][nt][0], acc[mt][nt][1]);
            float2 v8 = make_float2(acc[mt][nt][2], acc[mt][nt][3]);
            *reinterpret_cast<float2*>(&g_h[(size_t)(bm + r0) * OUT_C + col]) = v0;
            *reinterpret_cast<float2*>(&g_h[(size_t)(bm + r8) * OUT_C + col]) = v8;
            sl0 += alv[nt][0] * v0.x + alv[nt][1] * v0.y;
            sl8 += alv[nt][0] * v8.x + alv[nt][1] * v8.y;
            sr0 += arv[nt][0] * v0.x + arv[nt][1] * v0.y;
            sr8 += arv[nt][0] * v8.x + arv[nt][1] * v8.y;
        }
        #pragma unroll
        for (int off = 1; off < 4; off <<= 1) {
            sl0 += __shfl_xor_sync(0xffffffffu, sl0, off);
            sl8 += __shfl_xor_sync(0xffffffffu, sl8, off);
            sr0 += __shfl_xor_sync(0xffffffffu, sr0, off);
            sr8 += __shfl_xor_sync(0xffffffffu, sr8, off);
        }
        if ((lane & 3) == 0) {
            s_sl[r0][hdl][wp] = sl0;  s_sl[r8][hdl][wp] = sl8;
            s_sr[r0][hdl][wp] = sr0;  s_sr[r8][hdl][wp] = sr8;
        }
    }
    __syncthreads();

    if (tid < 128) {
        int gr = bm + tid;
        int hb = bn >> 6;
        g_sl[(size_t)gr * 4 + hb + 0] = s_sl[tid][0][0] + s_sl[tid][0][1];
        g_sl[(size_t)gr * 4 + hb + 1] = s_sl[tid][1][0] + s_sl[tid][1][1];
        g_sr[(size_t)gr * 4 + hb + 0] = s_sr[tid][0][0] + s_sr[tid][0][1];
        g_sr[(size_t)gr * 4 + hb + 1] = s_sr[tid][1][0] + s_sr[tid][1][1];
    }
}

// ---------------------------------------------------------------------------
// Kernel D: softmax + aggregation. Round-2 structure, gathers explicitly
// batched in groups of 4 (MLP=4) with NO occupancy cap (regs ~48, occ stays
// high). Only change vs the proven 54us version is the batched load loop.
// ---------------------------------------------------------------------------
__global__ __launch_bounds__(256) void gat_agg_kernel(
    const int*    __restrict__ col_ind,
    const float4* __restrict__ h4,
    const float4* __restrict__ sl4,
    const float4* __restrict__ sr4,
    float4*       __restrict__ out4)
{
    const int local = threadIdx.x >> 6;
    const int t     = threadIdx.x & 63;
    const int n     = blockIdx.x * 4 + local;

    __shared__ int   ssrc  [4][16];
    __shared__ float salpha[4][16][4];

    if (t < 16) {
        int s = col_ind[n * DEG + t];
        ssrc[local][t] = s;
        float4 l = sl4[n];
        float4 r = sr4[s];
        float e0 = l.x + r.x, e1 = l.y + r.y, e2 = l.z + r.z, e3 = l.w + r.w;
        e0 = (e0 > 0.f) ? e0 : NEG_SLOPE * e0;
        e1 = (e1 > 0.f) ? e1 : NEG_SLOPE * e1;
        e2 = (e2 > 0.f) ? e2 : NEG_SLOPE * e2;
        e3 = (e3 > 0.f) ? e3 : NEG_SLOPE * e3;
        float m0 = e0, m1 = e1, m2 = e2, m3 = e3;
        #pragma unroll
        for (int off = 8; off > 0; off >>= 1) {
            m0 = fmaxf(m0, __shfl_xor_sync(0xffffu, m0, off));
            m1 = fmaxf(m1, __shfl_xor_sync(0xffffu, m1, off));
            m2 = fmaxf(m2, __shfl_xor_sync(0xffffu, m2, off));
            m3 = fmaxf(m3, __shfl_xor_sync(0xffffu, m3, off));
        }
        float x0 = __expf(e0 - m0), x1 = __expf(e1 - m1);
        float x2 = __expf(e2 - m2), x3 = __expf(e3 - m3);
        float s0 = x0, s1 = x1, s2 = x2, s3 = x3;
        #pragma unroll
        for (int off = 8; off > 0; off >>= 1) {
            s0 += __shfl_xor_sync(0xffffu, s0, off);
            s1 += __shfl_xor_sync(0xffffu, s1, off);
            s2 += __shfl_xor_sync(0xffffu, s2, off);
            s3 += __shfl_xor_sync(0xffffu, s3, off);
        }
        *reinterpret_cast<float4*>(&salpha[local][t][0]) =
            make_float4(x0 / s0, x1 / s1, x2 / s2, x3 / s3);
    }
    __syncthreads();

    const int hd = t >> 4;
    float4 acc = make_float4(0.f, 0.f, 0.f, 0.f);
    #pragma unroll
    for (int kb = 0; kb < DEG; kb += 4) {
        // batch 4 gathers -> 4 outstanding LDG.128 before any FMA consumes them
        float4 v0 = h4[(size_t)ssrc[local][kb + 0] * 64 + t];
        float4 v1 = h4[(size_t)ssrc[local][kb + 1] * 64 + t];
        float4 v2 = h4[(size_t)ssrc[local][kb + 2] * 64 + t];
        float4 v3 = h4[(size_t)ssrc[local][kb + 3] * 64 + t];
        float a0 = salpha[local][kb + 0][hd];
        float a1 = salpha[local][kb + 1][hd];
        float a2 = salpha[local][kb + 2][hd];
        float a3 = salpha[local][kb + 3][hd];
        acc.x += a0 * v0.x;  acc.y += a0 * v0.y;  acc.z += a0 * v0.z;  acc.w += a0 * v0.w;
        acc.x += a1 * v1.x;  acc.y += a1 * v1.y;  acc.z += a1 * v1.z;  acc.w += a1 * v1.w;
        acc.x += a2 * v2.x;  acc.y += a2 * v2.y;  acc.z += a2 * v2.z;  acc.w += a2 * v2.w;
        acc.x += a3 * v3.x;  acc.y += a3 * v3.y;  acc.z += a3 * v3.z;  acc.w += a3 * v3.w;
    }
    out4[(size_t)n * 64 + t] = acc;
}

// ---------------------------------------------------------------------------
// Launch. Inputs: row_ptr, col_ind, col_ptr, row_ind, feat, W, attn_l, attn_r
// ---------------------------------------------------------------------------
extern "C" void kernel_launch(void* const* d_in, const int* in_sizes, int n_in,
                              void* d_out, int out_size)
{
    const int*   col_ind = (const int*)  d_in[1];
    const float* feat    = (const float*)d_in[4];
    const float* W       = (const float*)d_in[5];
    const float* attn_l  = (const float*)d_in[6];
    const float* attn_r  = (const float*)d_in[7];
    float*       out     = (float*)      d_out;

    const int M = in_sizes[4] / IN_F;    // 50000

    float *h_ptr = nullptr, *sl_ptr = nullptr, *sr_ptr = nullptr;
    cudaGetSymbolAddress((void**)&h_ptr,  g_h);
    cudaGetSymbolAddress((void**)&sl_ptr, g_sl);
    cudaGetSymbolAddress((void**)&sr_ptr, g_sr);

    dim3 gtw(IN_F / 32, OUT_C / 32);
    gat_transpose_w<<<gtw, 256>>>(W);

    dim3 gmm(N_PAD / 128, 2);
    gat_mma_kernel<<<gmm, 256>>>(feat, attn_l, attn_r, M);

    gat_agg_kernel<<<M / 4, 256>>>(col_ind,
                                   (const float4*)h_ptr,
                                   (const float4*)sl_ptr,
                                   (const float4*)sr_ptr,
                                   (float4*)out);
}

// round 11
// speedup vs baseline: 1.4051x; 1.1015x over previous
#include <cuda_runtime.h>
#include <cuda_bf16.h>
#include <cuda_fp16.h>
#include <cstdint>

#define N_NODES   50000
#define N_PAD     50048          // 391 * 128
#define DEG       16
#define IN_F      256
#define OUT_C     256            // NUM_HEADS * OUT_FEATS
#define NUM_HEADS 4
#define OUT_F     64
#define NEG_SLOPE 0.2f

// ---------------- scratch (static device globals; no allocation) ------------
__device__ float  g_wt[(size_t)OUT_C * IN_F];           // W^T [n][k], tf32-rounded
__device__ __half g_hh[(size_t)N_PAD * OUT_C];          // projected features (fp16)
__device__ float  g_sl[(size_t)N_PAD * NUM_HEADS];      // dst scores (fp32)
__device__ float  g_sr[(size_t)N_PAD * NUM_HEADS];      // src scores (fp32)

__device__ __forceinline__ uint32_t smem_u32(const void* p) {
    uint32_t a;
    asm("{ .reg .u64 t; cvta.to.shared.u64 t, %1; cvt.u32.u64 %0, t; }" : "=r"(a) : "l"(p));
    return a;
}

__device__ __forceinline__ void ldsm_x4(uint32_t* f, uint32_t addr) {
    asm volatile("ldmatrix.sync.aligned.m8n8.x4.shared.b16 {%0,%1,%2,%3}, [%4];"
                 : "=r"(f[0]), "=r"(f[1]), "=r"(f[2]), "=r"(f[3]) : "r"(addr));
}

__device__ __forceinline__ void mma_tf32(float* c, const uint32_t* a,
                                         uint32_t b0, uint32_t b1) {
    asm volatile("mma.sync.aligned.m16n8k8.row.col.f32.tf32.tf32.f32 "
                 "{%0,%1,%2,%3}, {%4,%5,%6,%7}, {%8,%9}, {%0,%1,%2,%3};"
                 : "+f"(c[0]), "+f"(c[1]), "+f"(c[2]), "+f"(c[3])
                 : "r"(a[0]), "r"(a[1]), "r"(a[2]), "r"(a[3]), "r"(b0), "r"(b1));
}

__device__ __forceinline__ float to_tf32(float x) {
    uint32_t u;
    asm("cvt.rna.tf32.f32 %0, %1;" : "=r"(u) : "f"(x));
    return __uint_as_float(u);
}

// ---------------------------------------------------------------------------
// Kernel B: transpose W [k][n] -> g_wt [n][k], tf32-rounded (256KB, ~4us)
// ---------------------------------------------------------------------------
__global__ __launch_bounds__(256) void gat_transpose_w(const float* __restrict__ W)
{
    __shared__ float tile[32][33];
    const int bk = blockIdx.x * 32;
    const int bn = blockIdx.y * 32;
    const int tx = threadIdx.x & 31;
    const int ty = threadIdx.x >> 5;
    #pragma unroll
    for (int j = 0; j < 32; j += 8)
        tile[ty + j][tx] = W[(size_t)(bk + ty + j) * OUT_C + bn + tx];
    __syncthreads();
    #pragma unroll
    for (int j = 0; j < 32; j += 8)
        g_wt[(size_t)(bn + ty + j) * IN_F + bk + tx] = to_tf32(tile[tx][ty + j]);
}

// ---------------------------------------------------------------------------
// Kernel C (round-6 proven mainloop): 1xTF32 mma.sync GEMM h = feat @ W.
// CTA = 128(M) x 128(N); 8 warps 2(m) x 4(n); warp tile 64x32; k-chunk 32.
// Static smem, stride 36 f32, single-buffered, 2 CTAs/SM.
// Epilogue: h stored as FP16 (gather payload) + fused fp32 attn score dots.
// ---------------------------------------------------------------------------
#define ASTR 36

__global__ __launch_bounds__(256, 2) void gat_mma_kernel(
    const float* __restrict__ feat,
    const float* __restrict__ attn_l,
    const float* __restrict__ attn_r,
    int M)
{
    __shared__ __align__(16) float sA[128 * ASTR];
    __shared__ __align__(16) float sB[128 * ASTR];
    __shared__ float s_sl[128][2][2];
    __shared__ float s_sr[128][2][2];

    const int tid  = threadIdx.x;
    const int wid  = tid >> 5;
    const int lane = tid & 31;
    const int bm   = blockIdx.x * 128;
    const int bn   = blockIdx.y * 128;
    const int wm   = wid >> 2;
    const int wn   = wid & 3;

    const uint32_t sA_b = smem_u32(sA);
    const uint32_t sB_b = smem_u32(sB);

    float acc[4][4][4];
    #pragma unroll
    for (int mt = 0; mt < 4; mt++)
        #pragma unroll
        for (int nt = 0; nt < 4; nt++)
            #pragma unroll
            for (int r = 0; r < 4; r++) acc[mt][nt][r] = 0.f;

    const int lrow = tid >> 1;
    const int lcol = (tid & 1) * 16;
    const bool arow_ok = (bm + lrow) < M;
    const float* aptr = feat + (size_t)(bm + lrow) * IN_F + lcol;
    const float* bptr = g_wt + (size_t)(bn + lrow) * IN_F + lcol;
    float* const sA_st = sA + lrow * ASTR + lcol;
    float* const sB_st = sB + lrow * ASTR + lcol;

    const int mi  = lane >> 3;
    const int aro = ((mi & 1) << 3) + (lane & 7);
    const int aco = (mi >> 1) << 2;
    const int bro = ((mi >> 1) << 3) + (lane & 7);
    const int bco = (mi & 1) << 2;

    for (int c = 0; c < 8; c++) {
        __syncthreads();
        {
            float4 a0, a1, a2, a3;
            if (arow_ok) {
                a0 = *reinterpret_cast<const float4*>(aptr + c * 32);
                a1 = *reinterpret_cast<const float4*>(aptr + c * 32 + 4);
                a2 = *reinterpret_cast<const float4*>(aptr + c * 32 + 8);
                a3 = *reinterpret_cast<const float4*>(aptr + c * 32 + 12);
            } else {
                a0 = a1 = a2 = a3 = make_float4(0.f, 0.f, 0.f, 0.f);
            }
            float4 b0 = *reinterpret_cast<const float4*>(bptr + c * 32);
            float4 b1 = *reinterpret_cast<const float4*>(bptr + c * 32 + 4);
            float4 b2 = *reinterpret_cast<const float4*>(bptr + c * 32 + 8);
            float4 b3 = *reinterpret_cast<const float4*>(bptr + c * 32 + 12);
            *reinterpret_cast<float4*>(sA_st)      = make_float4(to_tf32(a0.x), to_tf32(a0.y), to_tf32(a0.z), to_tf32(a0.w));
            *reinterpret_cast<float4*>(sA_st + 4)  = make_float4(to_tf32(a1.x), to_tf32(a1.y), to_tf32(a1.z), to_tf32(a1.w));
            *reinterpret_cast<float4*>(sA_st + 8)  = make_float4(to_tf32(a2.x), to_tf32(a2.y), to_tf32(a2.z), to_tf32(a2.w));
            *reinterpret_cast<float4*>(sA_st + 12) = make_float4(to_tf32(a3.x), to_tf32(a3.y), to_tf32(a3.z), to_tf32(a3.w));
            *reinterpret_cast<float4*>(sB_st)      = b0;
            *reinterpret_cast<float4*>(sB_st + 4)  = b1;
            *reinterpret_cast<float4*>(sB_st + 8)  = b2;
            *reinterpret_cast<float4*>(sB_st + 12) = b3;
        }
        __syncthreads();

        #pragma unroll
        for (int ks = 0; ks < 4; ks++) {
            uint32_t af[4][4];
            uint32_t bf[2][4];
            #pragma unroll
            for (int bp = 0; bp < 2; bp++) {
                int r = wn * 32 + bp * 16 + bro;
                uint32_t off = (uint32_t)(r * ASTR + ks * 8 + bco) * 4;
                ldsm_x4(bf[bp], sB_b + off);
            }
            #pragma unroll
            for (int mt = 0; mt < 4; mt++) {
                int r = wm * 64 + mt * 16 + aro;
                uint32_t off = (uint32_t)(r * ASTR + ks * 8 + aco) * 4;
                ldsm_x4(af[mt], sA_b + off);
            }
            #pragma unroll
            for (int mt = 0; mt < 4; mt++)
                #pragma unroll
                for (int nt = 0; nt < 4; nt++)
                    mma_tf32(acc[mt][nt], af[mt],
                             bf[nt >> 1][(nt & 1) * 2],
                             bf[nt >> 1][(nt & 1) * 2 + 1]);
        }
    }

    // ---- epilogue: store h as fp16 + fused fp32 score dots ------------------
    const int hdl = wn >> 1;
    const int wp  = wn & 1;

    float alv[4][2], arv[4][2];
    #pragma unroll
    for (int nt = 0; nt < 4; nt++) {
        int col = bn + wn * 32 + nt * 8 + (lane & 3) * 2;
        alv[nt][0] = attn_l[col];     alv[nt][1] = attn_l[col + 1];
        arv[nt][0] = attn_r[col];     arv[nt][1] = attn_r[col + 1];
    }

    #pragma unroll
    for (int mt = 0; mt < 4; mt++) {
        int r0 = wm * 64 + mt * 16 + (lane >> 2);
        int r8 = r0 + 8;
        float sl0 = 0.f, sl8 = 0.f, sr0 = 0.f, sr8 = 0.f;
        #pragma unroll
        for (int nt = 0; nt < 4; nt++) {
            int col = bn + wn * 32 + nt * 8 + (lane & 3) * 2;
            float2 v0 = make_float2(acc[mt][nt][0], acc[mt][nt][1]);
            float2 v8 = make_float2(acc[mt][nt][2], acc[mt][nt][3]);
            __half2 p0 = __floats2half2_rn(v0.x, v0.y);
            __half2 p8 = __floats2half2_rn(v8.x, v8.y);
            *reinterpret_cast<__half2*>(&g_hh[(size_t)(bm + r0) * OUT_C + col]) = p0;
            *reinterpret_cast<__half2*>(&g_hh[(size_t)(bm + r8) * OUT_C + col]) = p8;
            sl0 += alv[nt][0] * v0.x + alv[nt][1] * v0.y;
            sl8 += alv[nt][0] * v8.x + alv[nt][1] * v8.y;
            sr0 += arv[nt][0] * v0.x + arv[nt][1] * v0.y;
            sr8 += arv[nt][0] * v8.x + arv[nt][1] * v8.y;
        }
        #pragma unroll
        for (int off = 1; off < 4; off <<= 1) {
            sl0 += __shfl_xor_sync(0xffffffffu, sl0, off);
            sl8 += __shfl_xor_sync(0xffffffffu, sl8, off);
            sr0 += __shfl_xor_sync(0xffffffffu, sr0, off);
            sr8 += __shfl_xor_sync(0xffffffffu, sr8, off);
        }
        if ((lane & 3) == 0) {
            s_sl[r0][hdl][wp] = sl0;  s_sl[r8][hdl][wp] = sl8;
            s_sr[r0][hdl][wp] = sr0;  s_sr[r8][hdl][wp] = sr8;
        }
    }
    __syncthreads();

    if (tid < 128) {
        int gr = bm + tid;
        int hb = bn >> 6;
        g_sl[(size_t)gr * 4 + hb + 0] = s_sl[tid][0][0] + s_sl[tid][0][1];
        g_sl[(size_t)gr * 4 + hb + 1] = s_sl[tid][1][0] + s_sl[tid][1][1];
        g_sr[(size_t)gr * 4 + hb + 0] = s_sr[tid][0][0] + s_sr[tid][0][1];
        g_sr[(size_t)gr * 4 + hb + 1] = s_sr[tid][1][0] + s_sr[tid][1][1];
    }
}

// ---------------------------------------------------------------------------
// Kernel D: softmax (fp32 scores, unchanged) + fp16-gather aggregation.
// 64 threads per node, 4 nodes per block. Thread t owns output features
// 4t..4t+3 and gathers them as 4 halves (LDG.64) -> halved L1/L2 traffic.
// ---------------------------------------------------------------------------
__global__ __launch_bounds__(256) void gat_agg_kernel(
    const int*    __restrict__ col_ind,
    const uint2*  __restrict__ hh2,    // g_hh viewed as [N][64] x (4 halves)
    const float4* __restrict__ sl4,
    const float4* __restrict__ sr4,
    float4*       __restrict__ out4)
{
    const int local = threadIdx.x >> 6;
    const int t     = threadIdx.x & 63;
    const int n     = blockIdx.x * 4 + local;

    __shared__ int   ssrc  [4][16];
    __shared__ float salpha[4][16][4];

    if (t < 16) {
        int s = col_ind[n * DEG + t];
        ssrc[local][t] = s;
        float4 l = sl4[n];
        float4 r = sr4[s];
        float e0 = l.x + r.x, e1 = l.y + r.y, e2 = l.z + r.z, e3 = l.w + r.w;
        e0 = (e0 > 0.f) ? e0 : NEG_SLOPE * e0;
        e1 = (e1 > 0.f) ? e1 : NEG_SLOPE * e1;
        e2 = (e2 > 0.f) ? e2 : NEG_SLOPE * e2;
        e3 = (e3 > 0.f) ? e3 : NEG_SLOPE * e3;
        float m0 = e0, m1 = e1, m2 = e2, m3 = e3;
        #pragma unroll
        for (int off = 8; off > 0; off >>= 1) {
            m0 = fmaxf(m0, __shfl_xor_sync(0xffffu, m0, off));
            m1 = fmaxf(m1, __shfl_xor_sync(0xffffu, m1, off));
            m2 = fmaxf(m2, __shfl_xor_sync(0xffffu, m2, off));
            m3 = fmaxf(m3, __shfl_xor_sync(0xffffu, m3, off));
        }
        float x0 = __expf(e0 - m0), x1 = __expf(e1 - m1);
        float x2 = __expf(e2 - m2), x3 = __expf(e3 - m3);
        float s0 = x0, s1 = x1, s2 = x2, s3 = x3;
        #pragma unroll
        for (int off = 8; off > 0; off >>= 1) {
            s0 += __shfl_xor_sync(0xffffu, s0, off);
            s1 += __shfl_xor_sync(0xffffu, s1, off);
            s2 += __shfl_xor_sync(0xffffu, s2, off);
            s3 += __shfl_xor_sync(0xffffu, s3, off);
        }
        *reinterpret_cast<float4*>(&salpha[local][t][0]) =
            make_float4(x0 / s0, x1 / s1, x2 / s2, x3 / s3);
    }
    __syncthreads();

    const int hd = t >> 4;
    float4 acc = make_float4(0.f, 0.f, 0.f, 0.f);
    #pragma unroll
    for (int k = 0; k < DEG; k++) {
        float a  = salpha[local][k][hd];
        uint2 u  = hh2[(size_t)ssrc[local][k] * 64 + t];
        float2 f01 = __half22float2(*reinterpret_cast<__half2*>(&u.x));
        float2 f23 = __half22float2(*reinterpret_cast<__half2*>(&u.y));
        acc.x += a * f01.x;
        acc.y += a * f01.y;
        acc.z += a * f23.x;
        acc.w += a * f23.y;
    }
    out4[(size_t)n * 64 + t] = acc;
}

// ---------------------------------------------------------------------------
// Launch. Inputs: row_ptr, col_ind, col_ptr, row_ind, feat, W, attn_l, attn_r
// ---------------------------------------------------------------------------
extern "C" void kernel_launch(void* const* d_in, const int* in_sizes, int n_in,
                              void* d_out, int out_size)
{
    const int*   col_ind = (const int*)  d_in[1];
    const float* feat    = (const float*)d_in[4];
    const float* W       = (const float*)d_in[5];
    const float* attn_l  = (const float*)d_in[6];
    const float* attn_r  = (const float*)d_in[7];
    float*       out     = (float*)      d_out;

    const int M = in_sizes[4] / IN_F;    // 50000

    __half* hh_ptr = nullptr;
    float  *sl_ptr = nullptr, *sr_ptr = nullptr;
    cudaGetSymbolAddress((void**)&hh_ptr, g_hh);
    cudaGetSymbolAddress((void**)&sl_ptr, g_sl);
    cudaGetSymbolAddress((void**)&sr_ptr, g_sr);

    dim3 gtw(IN_F / 32, OUT_C / 32);
    gat_transpose_w<<<gtw, 256>>>(W);

    dim3 gmm(N_PAD / 128, 2);
    gat_mma_kernel<<<gmm, 256>>>(feat, attn_l, attn_r, M);

    gat_agg_kernel<<<M / 4, 256>>>(col_ind,
                                   (const uint2*)hh_ptr,
                                   (const float4*)sl_ptr,
                                   (const float4*)sr_ptr,
                                   (float4*)out);
}